// round 15
// baseline (speedup 1.0000x reference)
#include <cuda_runtime.h>
#include <cuda_fp16.h>

#define BATCH 2
#define FH 50
#define FW 75
#define CH 512
#define HW (FH * FW)          // 3750
#define PH 8
#define PW 8
#define NTHREADS 128          // 2 channels per thread, 256 channels per CTA
#define CH_PER_CTA 256
#define NPAIRS (CH_PER_CTA / 2)
#define OUT_PER_ROI (CH * 7 * 7)            // 25088 elements
#define STRIDE 29                           // halves per channel in staging (odd)
#define SMEM_BYTES (CH_PER_CTA * STRIDE * 2)  // 14848 bytes
#define SPATIAL_SCALE (1.0f / 16.0f)

// NHWC fp16 scratch: 2 * 3750 * 512 * 2B = 7.68 MB (deep in L2)
__device__ __half g_feat_hwc[BATCH * HW * CH];

// ---------------------------------------------------------------------------
// Kernel 1: NCHW fp32 -> NHWC fp16 transpose.
// ---------------------------------------------------------------------------
__global__ void transpose_nchw_nhwc(const float* __restrict__ in) {
    __shared__ float tile[32][33];
    const int b   = blockIdx.z;
    const int hw0 = blockIdx.x * 32;
    const int c0  = blockIdx.y * 32;

    const float* src = in + (size_t)b * CH * HW;
    __half*      dst = g_feat_hwc + (size_t)b * HW * CH;

    #pragma unroll
    for (int t = 0; t < 32; t += 8) {
        int c  = c0 + threadIdx.y + t;
        int hw = hw0 + threadIdx.x;
        if (hw < HW)
            tile[threadIdx.y + t][threadIdx.x] = src[(size_t)c * HW + hw];
    }
    __syncthreads();

    const int tid = threadIdx.y * 32 + threadIdx.x;   // 0..255
    #pragma unroll
    for (int t = 0; t < 2; t++) {
        const int idx    = t * 256 + tid;   // 0..511
        const int hw_off = idx >> 4;        // 0..31
        const int cpair  = idx & 15;        // 0..15
        const int hw     = hw0 + hw_off;
        if (hw < HW) {
            __half2 v = __floats2half2_rn(tile[2 * cpair][hw_off],
                                          tile[2 * cpair + 1][hw_off]);
            *(__half2*)(dst + (size_t)hw * CH + c0 + 2 * cpair) = v;
        }
    }
}

// ---------------------------------------------------------------------------
// Kernel 2: grid (n_rois, 2). Each CTA = half a roi's channels.
// 128 threads = 2 channels each (half2 packed). half2 loads + half2 math.
// Chunked fp16 staging (rows 0-3, then rows 4-6) in a 14.8 KB buffer ->
// 10 CTAs/SM target (reg-capped at 51 via launch_bounds).
// ---------------------------------------------------------------------------
__global__ __launch_bounds__(NTHREADS, 10)
void roi_plus_avg_kernel(const float* __restrict__ rois,
                         float* __restrict__ out) {
    extern __shared__ __half s_out[];   // CH_PER_CTA * STRIDE halves

    const int n     = blockIdx.x;
    const int half  = blockIdx.y;                  // channel half: 0 or 1
    const int cbase = half * CH_PER_CTA;
    const int cloc  = threadIdx.x * 2;             // local channel pair
    const int c0    = cbase + cloc;                // global channel

    __shared__ int     s_hs[PH], s_ws[PW];
    __shared__ __half2 s_hr2[PH], s_wr2[PW];
    __shared__ int     s_hv[PH], s_wv[PW];
    __shared__ int     s_b;

    if (threadIdx.x < PH) {
        const int i = threadIdx.x;
        const float x1 = rois[n * 5 + 1] * SPATIAL_SCALE;
        const float y1 = rois[n * 5 + 2] * SPATIAL_SCALE;
        const float x2 = rois[n * 5 + 3] * SPATIAL_SCALE;
        const float y2 = rois[n * 5 + 4] * SPATIAL_SCALE;
        const float roi_w = fmaxf(x2 - x1 + 1.0f, 0.0f);
        const float roi_h = fmaxf(y2 - y1 + 1.0f, 0.0f);
        const float bin_h = roi_h * (1.0f / (PH - 1));
        const float bin_w = roi_w * (1.0f / (PW - 1));

        const float hh = y1 + (float)i * bin_h;
        const float ww = x1 + (float)i * bin_w;

        s_hv[i] = (hh >= 0.0f) && (hh < (float)FH);
        s_wv[i] = (ww >= 0.0f) && (ww < (float)FW);

        int hs = (int)floorf(hh);
        int ws = (int)floorf(ww);
        hs = min(max(hs, 0), FH - 2);
        ws = min(max(ws, 0), FW - 2);
        s_hs[i] = hs;
        s_ws[i] = ws;
        s_hr2[i] = __float2half2_rn(hh - (float)hs);
        s_wr2[i] = __float2half2_rn(ww - (float)ws);

        if (i == 0) s_b = (int)rois[n * 5 + 0];
    }
    __syncthreads();

    const __half* fb = g_feat_hwc + (size_t)s_b * HW * CH + c0;
    const __half2 zero2 = __float2half2_rn(0.0f);
    const __half2 quarter2 = __float2half2_rn(0.25f);

    float* dstf = out + (size_t)n * OUT_PER_ROI + (size_t)cbase * 49;

    __half2 prev[PW];
    __half2 cur[PW];

    // ---- sample row i, pool with prev, stage at staging row p0 ----
    #define SAMPLE_ROW(i)                                                    \
    {                                                                        \
        const int     hs  = s_hs[i];                                         \
        const __half2 hr2 = s_hr2[i];                                        \
        const bool    hv  = (s_hv[i] != 0);                                  \
        const __half* r0 = fb + (size_t)(hs * FW) * CH;                      \
        const __half* r1 = r0 + (size_t)FW * CH;                             \
        _Pragma("unroll")                                                    \
        for (int j = 0; j < PW; j++) {                                       \
            __half2 v = zero2;                                               \
            if (hv && s_wv[j]) {                                             \
                const int     ws  = s_ws[j];                                 \
                const __half2 wr2 = s_wr2[j];                                \
                const __half2 ul = __ldg((const __half2*)(r0 + (size_t)ws * CH));       \
                const __half2 ur = __ldg((const __half2*)(r0 + (size_t)(ws + 1) * CH)); \
                const __half2 ll = __ldg((const __half2*)(r1 + (size_t)ws * CH));       \
                const __half2 lr = __ldg((const __half2*)(r1 + (size_t)(ws + 1) * CH)); \
                const __half2 top = __hfma2(__hsub2(ur, ul), wr2, ul);       \
                const __half2 bot = __hfma2(__hsub2(lr, ll), wr2, ll);       \
                v = __hfma2(__hsub2(bot, top), hr2, top);                    \
            }                                                                \
            cur[j] = v;                                                      \
        }                                                                    \
    }

    #define POOL_STAGE(p0)                                                   \
    {                                                                        \
        __half* o0 = s_out + cloc * STRIDE + (p0);                           \
        __half* o1 = o0 + STRIDE;                                            \
        _Pragma("unroll")                                                    \
        for (int j = 0; j < 7; j++) {                                        \
            const __half2 s = __hmul2(                                       \
                __hadd2(__hadd2(prev[j], prev[j + 1]),                       \
                        __hadd2(cur[j],  cur[j + 1])),                       \
                quarter2);                                                   \
            o0[j] = __low2half(s);                                           \
            o1[j] = __high2half(s);                                          \
        }                                                                    \
        _Pragma("unroll")                                                    \
        for (int j = 0; j < PW; j++) prev[j] = cur[j];                       \
    }

    // Phase 1: sample rows 0..4 -> pooled rows 0..3 staged at p = r*7
    SAMPLE_ROW(0);
    #pragma unroll
    for (int j = 0; j < PW; j++) prev[j] = cur[j];
    #pragma unroll
    for (int i = 1; i <= 4; i++) {
        SAMPLE_ROW(i);
        POOL_STAGE((i - 1) * 7);
    }
    __syncthreads();

    // Copy out pooled rows 0..3: 256 ch x 28 floats
    {
        const int N1 = CH_PER_CTA * 28;
        for (int idx = threadIdx.x; idx < N1; idx += NTHREADS) {
            const int c = idx / 28;
            const int p = idx - c * 28;
            dstf[c * 49 + p] = __half2float(s_out[c * STRIDE + p]);
        }
    }
    __syncthreads();

    // Phase 2: sample rows 5..7 -> pooled rows 4..6 staged at p = (r-4)*7
    #pragma unroll
    for (int i = 5; i <= 7; i++) {
        SAMPLE_ROW(i);
        POOL_STAGE((i - 5) * 7);
    }
    __syncthreads();

    // Copy out pooled rows 4..6: 256 ch x 21 floats
    {
        const int N2 = CH_PER_CTA * 21;
        for (int idx = threadIdx.x; idx < N2; idx += NTHREADS) {
            const int c = idx / 21;
            const int p = idx - c * 21;
            dstf[c * 49 + 28 + p] = __half2float(s_out[c * STRIDE + p]);
        }
    }

    #undef SAMPLE_ROW
    #undef POOL_STAGE
}

// ---------------------------------------------------------------------------
extern "C" void kernel_launch(void* const* d_in, const int* in_sizes, int n_in,
                              void* d_out, int out_size) {
    const float* features = (const float*)d_in[0];
    const float* rois     = (const float*)d_in[1];
    float*       out      = (float*)d_out;
    const int n_rois = in_sizes[1] / 5;

    cudaFuncSetAttribute(roi_plus_avg_kernel,
                         cudaFuncAttributeMaxDynamicSharedMemorySize,
                         SMEM_BYTES);

    dim3 tgrid((HW + 31) / 32, CH / 32, BATCH);
    dim3 tblk(32, 8);
    transpose_nchw_nhwc<<<tgrid, tblk>>>(features);

    dim3 rgrid(n_rois, 2);
    roi_plus_avg_kernel<<<rgrid, NTHREADS, SMEM_BYTES>>>(rois, out);
}

// round 16
// speedup vs baseline: 1.3344x; 1.3344x over previous
#include <cuda_runtime.h>
#include <cuda_fp16.h>

#define BATCH 2
#define FH 50
#define FW 75
#define CH 512
#define HW (FH * FW)          // 3750
#define PH 8
#define PW 8
#define NTHREADS 128          // 2 channels per thread, 256 channels per CTA
#define CH_PER_CTA 256
#define OUT_PER_ROI (CH * 7 * 7)            // 25088 elements
#define OUT_PER_CTA (CH_PER_CTA * 7 * 7)    // 12544 elements
#define SMEM_BYTES (OUT_PER_CTA * 2)        // 25088 bytes (fp16 staging)
#define SPATIAL_SCALE (1.0f / 16.0f)

// NHWC fp16 scratch: 2 * 3750 * 512 * 2B = 7.68 MB (deep in L2)
__device__ __half g_feat_hwc[BATCH * HW * CH];

// ---------------------------------------------------------------------------
// Kernel 1: NCHW fp32 -> NHWC fp16 transpose.
// ---------------------------------------------------------------------------
__global__ void transpose_nchw_nhwc(const float* __restrict__ in) {
    __shared__ float tile[32][33];
    const int b   = blockIdx.z;
    const int hw0 = blockIdx.x * 32;
    const int c0  = blockIdx.y * 32;

    const float* src = in + (size_t)b * CH * HW;
    __half*      dst = g_feat_hwc + (size_t)b * HW * CH;

    #pragma unroll
    for (int t = 0; t < 32; t += 8) {
        int c  = c0 + threadIdx.y + t;
        int hw = hw0 + threadIdx.x;
        if (hw < HW)
            tile[threadIdx.y + t][threadIdx.x] = src[(size_t)c * HW + hw];
    }
    __syncthreads();

    const int tid = threadIdx.y * 32 + threadIdx.x;   // 0..255
    #pragma unroll
    for (int t = 0; t < 2; t++) {
        const int idx    = t * 256 + tid;   // 0..511
        const int hw_off = idx >> 4;        // 0..31
        const int cpair  = idx & 15;        // 0..15
        const int hw     = hw0 + hw_off;
        if (hw < HW) {
            __half2 v = __floats2half2_rn(tile[2 * cpair][hw_off],
                                          tile[2 * cpair + 1][hw_off]);
            *(__half2*)(dst + (size_t)hw * CH + c0 + 2 * cpair) = v;
        }
    }
}

// ---------------------------------------------------------------------------
// Kernel 2: grid (n_rois, 2). Each CTA = half a roi's channels.
// 128 threads = 2 channels each (half2 packed). Unconditional half2 loads
// (clamped indices, validity applied as arithmetic mask -> no BSSY/BSYNC,
// full load batching), half2 interpolation/pooling, fp16 smem staging
// (identity layout -> pure linear uint4 copy-out).
// ---------------------------------------------------------------------------
__global__ __launch_bounds__(NTHREADS, 9)
void roi_plus_avg_kernel(const float* __restrict__ rois,
                         float* __restrict__ out) {
    extern __shared__ __half s_out[];   // OUT_PER_CTA halves

    const int n     = blockIdx.x;
    const int half  = blockIdx.y;                  // channel half: 0 or 1
    const int cbase = half * CH_PER_CTA;
    const int cloc  = threadIdx.x * 2;             // local channel pair
    const int c0    = cbase + cloc;                // global channel

    __shared__ int     s_hs[PH], s_ws[PW];
    __shared__ __half2 s_hr2[PH], s_wr2[PW];
    __shared__ __half2 s_hm2[PH], s_wm2[PW];       // validity masks (0 or 1)
    __shared__ int     s_b;

    if (threadIdx.x < PH) {
        const int i = threadIdx.x;
        const float x1 = rois[n * 5 + 1] * SPATIAL_SCALE;
        const float y1 = rois[n * 5 + 2] * SPATIAL_SCALE;
        const float x2 = rois[n * 5 + 3] * SPATIAL_SCALE;
        const float y2 = rois[n * 5 + 4] * SPATIAL_SCALE;
        const float roi_w = fmaxf(x2 - x1 + 1.0f, 0.0f);
        const float roi_h = fmaxf(y2 - y1 + 1.0f, 0.0f);
        const float bin_h = roi_h * (1.0f / (PH - 1));
        const float bin_w = roi_w * (1.0f / (PW - 1));

        const float hh = y1 + (float)i * bin_h;
        const float ww = x1 + (float)i * bin_w;

        const bool hv = (hh >= 0.0f) && (hh < (float)FH);
        const bool wv = (ww >= 0.0f) && (ww < (float)FW);
        s_hm2[i] = __float2half2_rn(hv ? 1.0f : 0.0f);
        s_wm2[i] = __float2half2_rn(wv ? 1.0f : 0.0f);

        int hs = (int)floorf(hh);
        int ws = (int)floorf(ww);
        hs = min(max(hs, 0), FH - 2);
        ws = min(max(ws, 0), FW - 2);
        s_hs[i] = hs;
        s_ws[i] = ws;
        s_hr2[i] = __float2half2_rn(hh - (float)hs);
        s_wr2[i] = __float2half2_rn(ww - (float)ws);

        if (i == 0) s_b = (int)rois[n * 5 + 0];
    }
    __syncthreads();

    const __half* fb = g_feat_hwc + (size_t)s_b * HW * CH + c0;
    const __half2 quarter2 = __float2half2_rn(0.25f);

    __half2 prev[PW];
    __half2 cur[PW];

    #pragma unroll
    for (int i = 0; i < PH; i++) {
        const int     hs  = s_hs[i];
        const __half2 hr2 = s_hr2[i];
        const __half2 hm2 = s_hm2[i];
        const __half* r0 = fb + (size_t)(hs * FW) * CH;
        const __half* r1 = r0 + (size_t)FW * CH;

        // Unconditional batched loads: 32 independent LDG.32 per row.
        __half2 ul[PW], ur[PW], ll[PW], lr[PW];
        #pragma unroll
        for (int j = 0; j < PW; j++) {
            const int ws = s_ws[j];
            ul[j] = __ldg((const __half2*)(r0 + (size_t)ws * CH));
            ur[j] = __ldg((const __half2*)(r0 + (size_t)(ws + 1) * CH));
            ll[j] = __ldg((const __half2*)(r1 + (size_t)ws * CH));
            lr[j] = __ldg((const __half2*)(r1 + (size_t)(ws + 1) * CH));
        }

        #pragma unroll
        for (int j = 0; j < PW; j++) {
            const __half2 wr2 = s_wr2[j];
            const __half2 top = __hfma2(__hsub2(ur[j], ul[j]), wr2, ul[j]);
            const __half2 bot = __hfma2(__hsub2(lr[j], ll[j]), wr2, ll[j]);
            const __half2 v   = __hfma2(__hsub2(bot, top), hr2, top);
            cur[j] = __hmul2(v, __hmul2(hm2, s_wm2[j]));   // arithmetic mask
        }

        if (i > 0) {
            // fp16 staging: local channel stride 49 halves (odd word stride ->
            // conflict-free STS.16); layout byte-matches global.
            __half* o0 = s_out + cloc * 49 + (i - 1) * 7;
            __half* o1 = o0 + 49;
            #pragma unroll
            for (int j = 0; j < 7; j++) {
                const __half2 s = __hmul2(
                    __hadd2(__hadd2(prev[j], prev[j + 1]),
                            __hadd2(cur[j],  cur[j + 1])),
                    quarter2);
                o0[j] = __low2half(s);
                o1[j] = __high2half(s);
            }
        }
        #pragma unroll
        for (int j = 0; j < PW; j++) prev[j] = cur[j];
    }

    __syncthreads();

    // Linear identity copy-out: read 8 halves (uint4), write 2 float4.
    // 12544 halves = 1568 uint4 chunks.
    float*       dstf = out + (size_t)n * OUT_PER_ROI + (size_t)cbase * 49;
    const uint4* src  = (const uint4*)s_out;
    for (int idx = threadIdx.x; idx < OUT_PER_CTA / 8; idx += NTHREADS) {
        const uint4 u = src[idx];
        const float2 a = __half22float2(*(const __half2*)&u.x);
        const float2 b = __half22float2(*(const __half2*)&u.y);
        const float2 c = __half22float2(*(const __half2*)&u.z);
        const float2 d = __half22float2(*(const __half2*)&u.w);
        float4* o4 = (float4*)(dstf + idx * 8);
        o4[0] = make_float4(a.x, a.y, b.x, b.y);
        o4[1] = make_float4(c.x, c.y, d.x, d.y);
    }
}

// ---------------------------------------------------------------------------
extern "C" void kernel_launch(void* const* d_in, const int* in_sizes, int n_in,
                              void* d_out, int out_size) {
    const float* features = (const float*)d_in[0];
    const float* rois     = (const float*)d_in[1];
    float*       out      = (float*)d_out;
    const int n_rois = in_sizes[1] / 5;

    cudaFuncSetAttribute(roi_plus_avg_kernel,
                         cudaFuncAttributeMaxDynamicSharedMemorySize,
                         SMEM_BYTES);

    dim3 tgrid((HW + 31) / 32, CH / 32, BATCH);
    dim3 tblk(32, 8);
    transpose_nchw_nhwc<<<tgrid, tblk>>>(features);

    dim3 rgrid(n_rois, 2);
    roi_plus_avg_kernel<<<rgrid, NTHREADS, SMEM_BYTES>>>(rois, out);
}

// round 17
// speedup vs baseline: 1.4923x; 1.1183x over previous
#include <cuda_runtime.h>
#include <cuda_fp16.h>

#define BATCH 2
#define FH 50
#define FW 75
#define CH 512
#define HW (FH * FW)          // 3750
#define PH 8
#define PW 8
#define NTHREADS 128          // 2 channels per thread, 256 channels per CTA
#define CH_PER_CTA 256
#define OUT_PER_ROI (CH * 7 * 7)            // 25088 elements
#define OUT_PER_CTA (CH_PER_CTA * 7 * 7)    // 12544 elements
#define SMEM_BYTES (OUT_PER_CTA * 2)        // 25088 bytes (fp16 staging)
#define SPATIAL_SCALE (1.0f / 16.0f)

// NHWC fp16 scratch: 2 * 3750 * 512 * 2B = 7.68 MB (deep in L2)
__device__ __half g_feat_hwc[BATCH * HW * CH];

// ---------------------------------------------------------------------------
// Kernel 1: NCHW fp32 -> NHWC fp16 transpose.
// ---------------------------------------------------------------------------
__global__ void transpose_nchw_nhwc(const float* __restrict__ in) {
    __shared__ float tile[32][33];
    const int b   = blockIdx.z;
    const int hw0 = blockIdx.x * 32;
    const int c0  = blockIdx.y * 32;

    const float* src = in + (size_t)b * CH * HW;
    __half*      dst = g_feat_hwc + (size_t)b * HW * CH;

    #pragma unroll
    for (int t = 0; t < 32; t += 8) {
        int c  = c0 + threadIdx.y + t;
        int hw = hw0 + threadIdx.x;
        if (hw < HW)
            tile[threadIdx.y + t][threadIdx.x] = src[(size_t)c * HW + hw];
    }
    __syncthreads();

    const int tid = threadIdx.y * 32 + threadIdx.x;   // 0..255
    #pragma unroll
    for (int t = 0; t < 2; t++) {
        const int idx    = t * 256 + tid;   // 0..511
        const int hw_off = idx >> 4;        // 0..31
        const int cpair  = idx & 15;        // 0..15
        const int hw     = hw0 + hw_off;
        if (hw < HW) {
            __half2 v = __floats2half2_rn(tile[2 * cpair][hw_off],
                                          tile[2 * cpair + 1][hw_off]);
            *(__half2*)(dst + (size_t)hw * CH + c0 + 2 * cpair) = v;
        }
    }
}

// ---------------------------------------------------------------------------
// Kernel 2: grid (n_rois, 2). Each CTA = half a roi's channels.
// 128 threads = 2 channels each (half2 packed). R14 structure: uniform
// branches (healthy MLP_p1), half2 loads + half2 math, fp16 smem staging
// with PAIRED STS.32 stores (parity-aware packing), linear uint4 copy-out.
// ---------------------------------------------------------------------------
__global__ __launch_bounds__(NTHREADS, 9)
void roi_plus_avg_kernel(const float* __restrict__ rois,
                         float* __restrict__ out) {
    extern __shared__ __half s_out[];   // OUT_PER_CTA halves

    const int n     = blockIdx.x;
    const int half  = blockIdx.y;                  // channel half: 0 or 1
    const int cbase = half * CH_PER_CTA;
    const int cloc  = threadIdx.x * 2;             // local channel pair (even)
    const int c0    = cbase + cloc;                // global channel

    __shared__ int     s_hs[PH], s_ws[PW];
    __shared__ __half2 s_hr2[PH], s_wr2[PW];
    __shared__ int     s_hv[PH], s_wv[PW];
    __shared__ int     s_b;

    if (threadIdx.x < PH) {
        const int i = threadIdx.x;
        const float x1 = rois[n * 5 + 1] * SPATIAL_SCALE;
        const float y1 = rois[n * 5 + 2] * SPATIAL_SCALE;
        const float x2 = rois[n * 5 + 3] * SPATIAL_SCALE;
        const float y2 = rois[n * 5 + 4] * SPATIAL_SCALE;
        const float roi_w = fmaxf(x2 - x1 + 1.0f, 0.0f);
        const float roi_h = fmaxf(y2 - y1 + 1.0f, 0.0f);
        const float bin_h = roi_h * (1.0f / (PH - 1));
        const float bin_w = roi_w * (1.0f / (PW - 1));

        const float hh = y1 + (float)i * bin_h;
        const float ww = x1 + (float)i * bin_w;

        s_hv[i] = (hh >= 0.0f) && (hh < (float)FH);
        s_wv[i] = (ww >= 0.0f) && (ww < (float)FW);

        int hs = (int)floorf(hh);
        int ws = (int)floorf(ww);
        hs = min(max(hs, 0), FH - 2);
        ws = min(max(ws, 0), FW - 2);
        s_hs[i] = hs;
        s_ws[i] = ws;
        s_hr2[i] = __float2half2_rn(hh - (float)hs);
        s_wr2[i] = __float2half2_rn(ww - (float)ws);

        if (i == 0) s_b = (int)rois[n * 5 + 0];
    }
    __syncthreads();

    const __half* fb = g_feat_hwc + (size_t)s_b * HW * CH + c0;
    const __half2 zero2 = __float2half2_rn(0.0f);
    const __half2 quarter2 = __float2half2_rn(0.25f);

    __half2 prev[PW];
    __half2 cur[PW];

    #pragma unroll
    for (int i = 0; i < PH; i++) {
        const int     hs  = s_hs[i];
        const __half2 hr2 = s_hr2[i];
        const bool    hv  = (s_hv[i] != 0);
        const __half* r0 = fb + (size_t)(hs * FW) * CH;
        const __half* r1 = r0 + (size_t)FW * CH;

        #pragma unroll
        for (int j = 0; j < PW; j++) {
            __half2 v = zero2;
            if (hv && s_wv[j]) {
                const int     ws  = s_ws[j];
                const __half2 wr2 = s_wr2[j];
                const __half2 ul = __ldg((const __half2*)(r0 + (size_t)ws * CH));
                const __half2 ur = __ldg((const __half2*)(r0 + (size_t)(ws + 1) * CH));
                const __half2 ll = __ldg((const __half2*)(r1 + (size_t)ws * CH));
                const __half2 lr = __ldg((const __half2*)(r1 + (size_t)(ws + 1) * CH));
                const __half2 top = __hfma2(__hsub2(ur, ul), wr2, ul);
                const __half2 bot = __hfma2(__hsub2(lr, ll), wr2, ll);
                v = __hfma2(__hsub2(bot, top), hr2, top);
            }
            cur[j] = v;
        }

        if (i > 0) {
            const int r = i - 1;              // pooled row (compile-time, loop unrolled)
            __half2 s[7];
            #pragma unroll
            for (int j = 0; j < 7; j++)
                s[j] = __hmul2(
                    __hadd2(__hadd2(prev[j], prev[j + 1]),
                            __hadd2(cur[j],  cur[j + 1])),
                    quarter2);

            // Staging: channel c -> s_out + c*49 + r*7 (identity layout).
            // Base parity: o0 (even channel) has parity(r); o1 = o0+49 flips.
            // Pack adjacent-j, same-channel values into half2 STS.32 where
            // the 4B alignment allows; scalars at the odd ends.
            __half* o0 = s_out + cloc * 49 + r * 7;
            __half* o1 = o0 + 49;
            if ((r & 1) == 0) {
                // o0 even-aligned: pairs at +0,+2,+4; scalar +6
                *(__half2*)(o0 + 0) = __lows2half2(s[0], s[1]);
                *(__half2*)(o0 + 2) = __lows2half2(s[2], s[3]);
                *(__half2*)(o0 + 4) = __lows2half2(s[4], s[5]);
                o0[6] = __low2half(s[6]);
                // o1 odd-aligned: scalar +0; pairs at +1,+3,+5
                o1[0] = __high2half(s[0]);
                *(__half2*)(o1 + 1) = __highs2half2(s[1], s[2]);
                *(__half2*)(o1 + 3) = __highs2half2(s[3], s[4]);
                *(__half2*)(o1 + 5) = __highs2half2(s[5], s[6]);
            } else {
                // o0 odd-aligned: scalar +0; pairs at +1,+3,+5
                o0[0] = __low2half(s[0]);
                *(__half2*)(o0 + 1) = __lows2half2(s[1], s[2]);
                *(__half2*)(o0 + 3) = __lows2half2(s[3], s[4]);
                *(__half2*)(o0 + 5) = __lows2half2(s[5], s[6]);
                // o1 even-aligned: pairs at +0,+2,+4; scalar +6
                *(__half2*)(o1 + 0) = __highs2half2(s[0], s[1]);
                *(__half2*)(o1 + 2) = __highs2half2(s[2], s[3]);
                *(__half2*)(o1 + 4) = __highs2half2(s[4], s[5]);
                o1[6] = __high2half(s[6]);
            }
        }
        #pragma unroll
        for (int j = 0; j < PW; j++) prev[j] = cur[j];
    }

    __syncthreads();

    // Linear identity copy-out: read 8 halves (uint4), write 2 float4.
    // 12544 halves = 1568 uint4 chunks.
    float*       dstf = out + (size_t)n * OUT_PER_ROI + (size_t)cbase * 49;
    const uint4* src  = (const uint4*)s_out;
    for (int idx = threadIdx.x; idx < OUT_PER_CTA / 8; idx += NTHREADS) {
        const uint4 u = src[idx];
        const float2 a = __half22float2(*(const __half2*)&u.x);
        const float2 b = __half22float2(*(const __half2*)&u.y);
        const float2 c = __half22float2(*(const __half2*)&u.z);
        const float2 d = __half22float2(*(const __half2*)&u.w);
        float4* o4 = (float4*)(dstf + idx * 8);
        o4[0] = make_float4(a.x, a.y, b.x, b.y);
        o4[1] = make_float4(c.x, c.y, d.x, d.y);
    }
}

// ---------------------------------------------------------------------------
extern "C" void kernel_launch(void* const* d_in, const int* in_sizes, int n_in,
                              void* d_out, int out_size) {
    const float* features = (const float*)d_in[0];
    const float* rois     = (const float*)d_in[1];
    float*       out      = (float*)d_out;
    const int n_rois = in_sizes[1] / 5;

    cudaFuncSetAttribute(roi_plus_avg_kernel,
                         cudaFuncAttributeMaxDynamicSharedMemorySize,
                         SMEM_BYTES);

    dim3 tgrid((HW + 31) / 32, CH / 32, BATCH);
    dim3 tblk(32, 8);
    transpose_nchw_nhwc<<<tgrid, tblk>>>(features);

    dim3 rgrid(n_rois, 2);
    roi_plus_avg_kernel<<<rgrid, NTHREADS, SMEM_BYTES>>>(rois, out);
}